// round 16
// baseline (speedup 1.0000x reference)
#include <cuda_runtime.h>
#include <cuda_bf16.h>
#include <cstdint>
#include <math.h>

#define Bsz 512
#define Ssz 256
#define Esz 256
#define Hsz 512
#define Gsz 1536
#define Lsz 8
#define MROWS (Ssz * Bsz)
#define NCTA 128

// ---------------- device-global scratch (no runtime alloc) ------------------
__device__ __align__(16) float g_gi[(size_t)MROWS * Gsz];
__device__ __align__(16) float g_hf[Bsz * Hsz];          // final h only
__device__ __align__(16) __nv_bfloat16 g_hb_hi[2][Bsz * Hsz];
__device__ __align__(16) __nv_bfloat16 g_hb_lo[2][Bsz * Hsz];
__device__ __align__(16) __nv_bfloat16 g_x_hi[(size_t)MROWS * Esz];
__device__ __align__(16) __nv_bfloat16 g_x_lo[(size_t)MROWS * Esz];
__device__ __align__(16) __nv_bfloat16 g_whh_hi[Gsz * Hsz];
__device__ __align__(16) __nv_bfloat16 g_whh_lo[Gsz * Hsz];
__device__ __align__(16) __nv_bfloat16 g_wih_hi[Gsz * Esz];
__device__ __align__(16) __nv_bfloat16 g_wih_lo[Gsz * Esz];
__device__ unsigned int g_bars[8 * 32];   // per-b-group counters, 128B apart

// ---------------- PTX helpers (base-target only) -----------------------------
__device__ __forceinline__ uint32_t smem_u32(const void* p) {
    uint32_t a;
    asm("{ .reg .u64 t; cvta.to.shared.u64 t, %1; cvt.u32.u64 %0, t; }" : "=r"(a) : "l"(p));
    return a;
}
__device__ __forceinline__ void cp16(uint32_t dst, const void* src) {
    asm volatile("cp.async.cg.shared.global [%0], [%1], 16;" :: "r"(dst), "l"(src));
}
#define CP_COMMIT() asm volatile("cp.async.commit_group;" ::: "memory")
#define CP_WAIT(n)  asm volatile("cp.async.wait_group %0;" :: "n"(n) : "memory")

#define LDMX4(r, addr) \
    asm volatile("ldmatrix.sync.aligned.m8n8.x4.shared.b16 {%0,%1,%2,%3}, [%4];" \
        : "=r"((r)[0]), "=r"((r)[1]), "=r"((r)[2]), "=r"((r)[3]) : "r"(addr))

#define LDMX2(r, addr) \
    asm volatile("ldmatrix.sync.aligned.m8n8.x2.shared.b16 {%0,%1}, [%2];" \
        : "=r"((r)[0]), "=r"((r)[1]) : "r"(addr))

#define MMA_BF16(c, a, b0, b1) \
    asm volatile("mma.sync.aligned.m16n8k16.row.col.f32.bf16.bf16.f32 " \
        "{%0,%1,%2,%3}, {%4,%5,%6,%7}, {%8,%9}, {%0,%1,%2,%3};" \
        : "+f"((c)[0]), "+f"((c)[1]), "+f"((c)[2]), "+f"((c)[3]) \
        : "r"((a)[0]), "r"((a)[1]), "r"((a)[2]), "r"((a)[3]), "r"(b0), "r"(b1))

// ---------------- split helpers ----------------------------------------------
__device__ __forceinline__ void split2(float v, __nv_bfloat16& h, __nv_bfloat16& l) {
    h = __float2bfloat16_rn(v);
    l = __float2bfloat16_rn(v - __bfloat162float(h));
}
__device__ __forceinline__ void split_store4(float4 v, __nv_bfloat16* dh, __nv_bfloat16* dl) {
    __nv_bfloat16 h0,l0,h1,l1,h2,l2,h3,l3;
    split2(v.x,h0,l0); split2(v.y,h1,l1); split2(v.z,h2,l2); split2(v.w,h3,l3);
    __nv_bfloat162 p;
    p.x=h0; p.y=h1; ((__nv_bfloat162*)dh)[0]=p;
    p.x=h2; p.y=h3; ((__nv_bfloat162*)dh)[1]=p;
    p.x=l0; p.y=l1; ((__nv_bfloat162*)dl)[0]=p;
    p.x=l2; p.y=l3; ((__nv_bfloat162*)dl)[1]=p;
}

// tiny no-op kernels: keep the ncu capture window on gru_persist_kernel
__global__ void noop_kernel() {}

// ---------------------------------------------------------------------------
// prep: x split, W_hh split, W_ih split, h0/bars init, one launch
// ---------------------------------------------------------------------------
__global__ void prep_kernel(const float* __restrict__ x,
                            const float* __restrict__ W_hh,
                            const float* __restrict__ W_ih) {
    int blk = blockIdx.x, tid = threadIdx.x;
    if (blk < 32768) {
        size_t t = (size_t)blk * 256 + tid;
        size_t m = t >> 6;
        int e4 = (int)(t & 63) << 2;
        int s = (int)(m >> 9), b = (int)(m & 511);
        float4 v = *(const float4*)(x + ((size_t)b * Ssz + s) * Esz + e4);
        split_store4(v, g_x_hi + m * Esz + e4, g_x_lo + m * Esz + e4);
    } else if (blk < 33536) {
        int t = (blk - 32768) * 256 + tid;
        float4 v = *(const float4*)(W_hh + (size_t)t * 4);
        split_store4(v, g_whh_hi + (size_t)t * 4, g_whh_lo + (size_t)t * 4);
    } else if (blk < 33920) {
        int t = (blk - 33536) * 256 + tid;
        float4 v = *(const float4*)(W_ih + (size_t)t * 4);
        split_store4(v, g_wih_hi + (size_t)t * 4, g_wih_lo + (size_t)t * 4);
    } else {
        int i = (blk - 33920) * 256 + tid;   // < Bsz*Hsz/2
        __nv_bfloat162 z;
        z.x = __float2bfloat16_rn(0.0f); z.y = z.x;
        ((__nv_bfloat162*)g_hb_hi[0])[i] = z;
        ((__nv_bfloat162*)g_hb_lo[0])[i] = z;
        if (blk == 33920 && tid < 256) g_bars[tid] = 0u;
    }
}

// ---------------------------------------------------------------------------
// gi GEMM (HMMA), R14 champion: 8 chunks of K=32, double-buffered, 2 CTAs/SM.
// ---------------------------------------------------------------------------
#define GI_CH   40960
#define GI_SMEM (2 * GI_CH)
#define GAH 0
#define GAL 10240
#define GBH 20480
#define GBL 30720

__global__ void __launch_bounds__(256) gi_mma_kernel(const float* __restrict__ b_ih) {
    extern __shared__ __align__(16) char dsm[];
    __shared__ float s_bias[128];
    uint32_t sbase = smem_u32(dsm);
    int tid = threadIdx.x, wid = tid >> 5, lane = tid & 31;
    int n0 = blockIdx.x * 128;
    int m0 = blockIdx.y * 128;
    if (tid < 128) s_bias[tid] = b_ih[n0 + tid];

    int m_warp = (wid & 1) * 64;
    int n_warp = (wid >> 1) * 32;

    float acc[4][4][4];
#pragma unroll
    for (int mi = 0; mi < 4; mi++)
#pragma unroll
        for (int ni = 0; ni < 4; ni++)
#pragma unroll
            for (int e = 0; e < 4; e++) acc[mi][ni][e] = 0.0f;

    auto issue = [&](int c, int q) {
        uint32_t base = sbase + (uint32_t)q * GI_CH;
        int k0 = c * 32;
        for (int i = tid; i < 2048; i += 256) {
            int arr = i >> 10;
            int half = (i >> 9) & 1;
            int idx = i & 511;
            int row = idx >> 2, seg = idx & 3;
            const __nv_bfloat16* sp;
            if (arr == 0)
                sp = (half ? g_x_lo : g_x_hi) + ((size_t)(m0 + row)) * Esz + k0 + seg * 8;
            else
                sp = (half ? g_wih_lo : g_wih_hi) + ((size_t)(n0 + row)) * Esz + k0 + seg * 8;
            uint32_t dst = base + (uint32_t)(arr * 20480 + half * 10240 + row * 80 + seg * 16);
            cp16(dst, sp);
        }
        CP_COMMIT();
    };

    issue(0, 0);
    for (int c = 0; c < 8; c++) {
        int q = c & 1;
        CP_WAIT(0);
        __syncthreads();
        if (c < 7) issue(c + 1, q ^ 1);
        uint32_t bb = sbase + (uint32_t)q * GI_CH;
#pragma unroll
        for (int kk = 0; kk < 2; kk++) {
            int kb = kk * 32;
            uint32_t fa[2][4][4];
#pragma unroll
            for (int mi = 0; mi < 4; mi++) {
                uint32_t arow = (uint32_t)(m_warp + mi * 16 + (lane & 15));
                uint32_t aoff = arow * 80 + kb + ((lane >> 4) << 4);
                LDMX4(fa[0][mi], bb + GAH + aoff);
                LDMX4(fa[1][mi], bb + GAL + aoff);
            }
            uint32_t fb[2][2][4];
#pragma unroll
            for (int p = 0; p < 2; p++) {
                uint32_t brow = (uint32_t)(n_warp + p * 16 + (lane & 7) + ((lane >> 4) << 3));
                uint32_t boff = brow * 80 + kb + (((lane >> 3) & 1) << 4);
                LDMX4(fb[0][p], bb + GBH + boff);
                LDMX4(fb[1][p], bb + GBL + boff);
            }
#pragma unroll
            for (int t = 0; t < 3; t++) {
                int sa = (t == 2) ? 1 : 0, sb = (t == 1) ? 1 : 0;
#pragma unroll
                for (int mi = 0; mi < 4; mi++)
#pragma unroll
                    for (int ni = 0; ni < 4; ni++)
                        MMA_BF16(acc[mi][ni], fa[sa][mi],
                                 fb[sb][ni >> 1][(ni & 1) * 2],
                                 fb[sb][ni >> 1][(ni & 1) * 2 + 1]);
            }
        }
    }

#pragma unroll
    for (int mi = 0; mi < 4; mi++) {
        int m = m0 + m_warp + mi * 16 + (lane >> 2);
#pragma unroll
        for (int ni = 0; ni < 4; ni++) {
            int nl = n_warp + ni * 8 + (lane & 3) * 2;
            float2 v0 = make_float2(acc[mi][ni][0] + s_bias[nl],
                                    acc[mi][ni][1] + s_bias[nl + 1]);
            float2 v1 = make_float2(acc[mi][ni][2] + s_bias[nl],
                                    acc[mi][ni][3] + s_bias[nl + 1]);
            *(float2*)(g_gi + (size_t)m * Gsz + n0 + nl) = v0;
            *(float2*)(g_gi + (size_t)(m + 8) * Gsz + n0 + nl) = v1;
        }
    }
}

// ---------------------------------------------------------------------------
// Persistent GRU recurrence, R16: split-K warp specialization.
// 512 threads = 2 halves of 8 warps. Half h computes K in [h*256,(h+1)*256)
// (4 chunks of 64), each half with its OWN 16KB h-buffer and named barrier,
// so the two halves hide each other's load latency (4 warps/SMSP).
// After the chunk phase: half1 -> smem (24KB, reuses dead h-buffers),
// half0 adds + runs the R15 register epilogue. Tiling per half = R15 2Mx4N.
// ---------------------------------------------------------------------------
#define WSPLIT 98304
#define WCHUNK 12288
#define WTOT   196608
#define HBUF   16384
#define HSPLIT 8192
#define PS_SMEM (WTOT + 2 * HBUF)   // 229376

__global__ void __launch_bounds__(512) gru_persist_kernel(
    const float* __restrict__ b_hh, const float* __restrict__ W_out,
    const float* __restrict__ b_out, float* __restrict__ out) {
    extern __shared__ __align__(16) char dsm[];
    __shared__ float s_bhh[96];
    uint32_t sbase = smem_u32(dsm);
    int tid = threadIdx.x, wid = tid >> 5, lane = tid & 31;
    int half = wid >> 3, hw = wid & 7;
    int ltid = tid & 255;
    int bx = blockIdx.x >> 4, jy = blockIdx.x & 15;
    int b0 = bx * 64, j0 = jy * 32;
    if (tid < 96) s_bhh[tid] = b_hh[(tid >> 5) * Hsz + j0 + (tid & 31)];

    // ---- resident W_hh tile: 12288 x 16B, XOR swizzle (512 threads) ----
    for (int i = tid; i < 12288; i += 512) {
        int p = i / 6144;
        int ii = i - p * 6144;
        int c = ii / 768;
        int r2 = ii - c * 768;
        int r = r2 >> 3, u = r2 & 7;
        int g = r >> 5, jr = r & 31;
        const __nv_bfloat16* sp = (p ? g_whh_lo : g_whh_hi) +
            ((size_t)(g * Hsz + j0 + jr)) * Hsz + c * 64 + u * 8;
        uint32_t dst = sbase + (uint32_t)(p * WSPLIT + c * WCHUNK + r * 128 +
                                          ((u ^ (r & 7)) << 4));
        cp16(dst, sp);
    }
    CP_COMMIT();
    CP_WAIT(0);
    __syncthreads();

    // 2M x 4N tiling within each half
    const int m_warp = (hw & 1) * 32;
    const int jq = hw >> 1;
    const int jb = jq * 8 + (lane & 3) * 2;
    const int jcol = j0 + jb;
    unsigned int* bar = &g_bars[bx * 32];
    const uint32_t hbase = sbase + WTOT + (uint32_t)half * HBUF;
    const int bar_id = 1 + half;

    // kk-invariant LDSM address parts
    uint32_t a_rowoff[2], a_rx[2];
#pragma unroll
    for (int mi = 0; mi < 2; mi++) {
        uint32_t arow = (uint32_t)(m_warp + mi * 16 + (lane & 15));
        a_rowoff[mi] = arow * 128;
        a_rx[mi] = arow & 7;
    }
    const uint32_t a_ub = (uint32_t)(lane >> 4);
    uint32_t b_rowoff[3], b_rx[3];
#pragma unroll
    for (int g = 0; g < 3; g++) {
        uint32_t brow = (uint32_t)(g * 32 + jq * 8 + (lane & 7));
        b_rowoff[g] = brow * 128;
        b_rx[g] = brow & 7;
    }
    const uint32_t b_ub = (uint32_t)((lane >> 3) & 1);

    float2 hp[2][2];
#pragma unroll
    for (int mi = 0; mi < 2; mi++)
#pragma unroll
        for (int ri = 0; ri < 2; ri++) hp[mi][ri] = make_float2(0.0f, 0.0f);

    float2 pg[3][2][2];
    auto prefetch_gi = [&](int s) {
        const float* base = g_gi + (size_t)s * Bsz * Gsz;
#pragma unroll
        for (int g = 0; g < 3; g++)
#pragma unroll
            for (int mi = 0; mi < 2; mi++)
#pragma unroll
                for (int ri = 0; ri < 2; ri++) {
                    int b = b0 + m_warp + mi * 16 + ri * 8 + (lane >> 2);
                    pg[g][mi][ri] = *(const float2*)(base + (size_t)b * Gsz +
                                                     g * Hsz + jcol);
                }
    };
    if (half == 0) prefetch_gi(0);

    for (int s = 0; s < Ssz; s++) {
        int pin = s & 1, pout = pin ^ 1;
        const __nv_bfloat16* ah = g_hb_hi[pin];
        const __nv_bfloat16* al = g_hb_lo[pin];

        auto issue_h = [&](int c) {
            for (int i = ltid; i < 1024; i += 256) {
                int p = i >> 9;
                int idx = i & 511;
                int row = idx >> 3, u = idx & 7;
                const __nv_bfloat16* sp = (p ? al : ah) +
                    ((size_t)(b0 + row)) * Hsz + c * 64 + u * 8;
                uint32_t dst = hbase + (uint32_t)(p * HSPLIT + row * 128 +
                                                  ((u ^ (row & 7)) << 4));
                cp16(dst, sp);
            }
            CP_COMMIT();
        };

        float acc[2][3][4];
#pragma unroll
        for (int mi = 0; mi < 2; mi++)
#pragma unroll
            for (int g = 0; g < 3; g++)
#pragma unroll
                for (int e = 0; e < 4; e++) acc[mi][g][e] = 0.0f;

        // ---- chunk phase: each half independently, single buffer ----
        for (int ci = 0; ci < 4; ci++) {
            int c = half * 4 + ci;
            issue_h(c);
            CP_WAIT(0);
            asm volatile("bar.sync %0, 256;" :: "r"(bar_id) : "memory");
            uint32_t wb = sbase + (uint32_t)c * WCHUNK;

            uint32_t fa[2][2][2][4];   // [fq][split][mi][4]
            uint32_t fb[2][2][3][2];   // [fq][split][gate][2]
            auto load_frags = [&](int kk, int fq) {
                uint32_t ua = (uint32_t)(kk * 2) + a_ub;
#pragma unroll
                for (int mi = 0; mi < 2; mi++) {
                    uint32_t offa = a_rowoff[mi] + ((ua ^ a_rx[mi]) << 4);
                    LDMX4(fa[fq][0][mi], hbase + offa);
                    LDMX4(fa[fq][1][mi], hbase + HSPLIT + offa);
                }
                uint32_t ub = (uint32_t)(kk * 2) + b_ub;
#pragma unroll
                for (int g = 0; g < 3; g++) {
                    uint32_t offb = b_rowoff[g] + ((ub ^ b_rx[g]) << 4);
                    LDMX2(fb[fq][0][g], wb + offb);
                    LDMX2(fb[fq][1][g], wb + WSPLIT + offb);
                }
            };

            load_frags(0, 0);
#pragma unroll
            for (int kk = 0; kk < 4; kk++) {
                int fq = kk & 1;
                if (kk < 3) load_frags(kk + 1, fq ^ 1);
#pragma unroll
                for (int t = 0; t < 3; t++) {
                    int sa = (t == 2) ? 1 : 0, sb = (t == 1) ? 1 : 0;
#pragma unroll
                    for (int mi = 0; mi < 2; mi++)
#pragma unroll
                        for (int g = 0; g < 3; g++)
                            MMA_BF16(acc[mi][g], fa[fq][sa][mi],
                                     fb[fq][sb][g][0], fb[fq][sb][g][1]);
                }
            }
            if (ci < 3)   // WAR: all of this half done reading before next issue
                asm volatile("bar.sync %0, 256;" :: "r"(bar_id) : "memory");
        }

        // ---- split-K reduce: half1 -> smem, half0 adds ----
        __syncthreads();
        float* scr = (float*)(dsm + WTOT);   // 24KB, reuses dead h-buffers
        if (half == 1) {
            float* a = &acc[0][0][0];
            float4* sc = (float4*)scr + (size_t)ltid * 6;
#pragma unroll
            for (int i = 0; i < 6; i++)
                sc[i] = make_float4(a[4*i], a[4*i+1], a[4*i+2], a[4*i+3]);
        }
        __syncthreads();

        if (half == 0) {
            float* a = &acc[0][0][0];
            const float4* sc = (const float4*)scr + (size_t)ltid * 6;
#pragma unroll
            for (int i = 0; i < 6; i++) {
                float4 v = sc[i];
                a[4*i] += v.x; a[4*i+1] += v.y; a[4*i+2] += v.z; a[4*i+3] += v.w;
            }

            // ---- register-resident GRU epilogue (fast-math sigmoid) ----
            __nv_bfloat16* hho = g_hb_hi[pout];
            __nv_bfloat16* hlo = g_hb_lo[pout];
#pragma unroll
            for (int mi = 0; mi < 2; mi++) {
#pragma unroll
                for (int ri = 0; ri < 2; ri++) {
                    int b = b0 + m_warp + mi * 16 + ri * 8 + (lane >> 2);
                    float hv[2];
#pragma unroll
                    for (int e = 0; e < 2; e++) {
                        float dr = acc[mi][0][ri * 2 + e] + s_bhh[jb + e];
                        float dz = acc[mi][1][ri * 2 + e] + s_bhh[32 + jb + e];
                        float dn = acc[mi][2][ri * 2 + e] + s_bhh[64 + jb + e];
                        float gi_r = e ? pg[0][mi][ri].y : pg[0][mi][ri].x;
                        float gi_z = e ? pg[1][mi][ri].y : pg[1][mi][ri].x;
                        float gi_n = e ? pg[2][mi][ri].y : pg[2][mi][ri].x;
                        float hprev = e ? hp[mi][ri].y : hp[mi][ri].x;
                        float r = __fdividef(1.0f, 1.0f + __expf(-(gi_r + dr)));
                        float z = __fdividef(1.0f, 1.0f + __expf(-(gi_z + dz)));
                        float n = tanhf(gi_n + r * dn);
                        hv[e] = (1.0f - z) * n + z * hprev;
                    }
                    hp[mi][ri] = make_float2(hv[0], hv[1]);
                    __nv_bfloat16 h0, l0, h1, l1;
                    split2(hv[0], h0, l0);
                    split2(hv[1], h1, l1);
                    __nv_bfloat162 ph, pl;
                    ph.x = h0; ph.y = h1;
                    pl.x = l0; pl.y = l1;
                    *(__nv_bfloat162*)(hho + (size_t)b * Hsz + jcol) = ph;
                    *(__nv_bfloat162*)(hlo + (size_t)b * Hsz + jcol) = pl;
                    if (s == Ssz - 1)
                        *(float2*)(g_hf + (size_t)b * Hsz + jcol) =
                            make_float2(hv[0], hv[1]);
                }
            }
        }

        // ---- publish (h stores visible), prefetch next gi, barrier wait ----
        __syncthreads();
        if (tid == 0) {
            asm volatile("red.release.gpu.global.add.u32 [%0], %1;"
                         :: "l"(bar), "r"(1u) : "memory");
        }
        if (half == 0 && s + 1 < Ssz) prefetch_gi(s + 1);

        if (tid == 0) {
            unsigned int target = (unsigned int)(s + 1) * 16u;
            unsigned int v;
            do {
                asm volatile("ld.acquire.gpu.u32 %0, [%1];" : "=r"(v) : "l"(bar));
            } while (v < target);
        }
        __syncthreads();
    }

    // ---- fused head: jy==0 CTAs, warps 0-7, rows b0..b0+63 ----
    if (jy == 0 && wid < 8) {
#pragma unroll 1
        for (int rr = 0; rr < 8; rr++) {
            int b = b0 + (wid << 3) + rr;
            const float* h = g_hf + (size_t)b * Hsz;
            float a8[Lsz];
#pragma unroll
            for (int l = 0; l < Lsz; l++) a8[l] = 0.0f;
            for (int j = lane; j < Hsz; j += 32) {
                float hv = h[j];
#pragma unroll
                for (int l = 0; l < Lsz; l++) a8[l] += hv * W_out[l * Hsz + j];
            }
#pragma unroll
            for (int l = 0; l < Lsz; l++)
#pragma unroll
                for (int o = 16; o > 0; o >>= 1)
                    a8[l] += __shfl_xor_sync(0xffffffff, a8[l], o);
            if (lane == 0) {
                float logits[Lsz], mx = -1e30f, sum = 0.0f;
#pragma unroll
                for (int l = 0; l < Lsz; l++) {
                    logits[l] = a8[l] + b_out[l];
                    mx = fmaxf(mx, logits[l]);
                }
#pragma unroll
                for (int l = 0; l < Lsz; l++) {
                    logits[l] = expf(logits[l] - mx);
                    sum += logits[l];
                }
                float inv = 1.0f / sum;
#pragma unroll
                for (int l = 0; l < Lsz; l++)
                    out[(size_t)b * Lsz + l] = logits[l] * inv;
            }
        }
    }
}

// ---------------------------------------------------------------------------
extern "C" void kernel_launch(void* const* d_in, const int* in_sizes, int n_in,
                              void* d_out, int out_size) {
    const float* x     = (const float*)d_in[0];
    const float* W_ih  = (const float*)d_in[1];
    const float* W_hh  = (const float*)d_in[2];
    const float* b_ih  = (const float*)d_in[3];
    const float* b_hh  = (const float*)d_in[4];
    const float* W_out = (const float*)d_in[5];
    const float* b_out = (const float*)d_in[6];
    float* out = (float*)d_out;

    cudaFuncSetAttribute(gi_mma_kernel, cudaFuncAttributeMaxDynamicSharedMemorySize, GI_SMEM);
    cudaFuncSetAttribute(gru_persist_kernel, cudaFuncAttributeMaxDynamicSharedMemorySize, PS_SMEM);

    // identical launch sequence so the ncu window stays on gru
    noop_kernel<<<1, 32>>>();
    prep_kernel<<<34432, 256>>>(x, W_hh, W_ih);
    gi_mma_kernel<<<dim3(Gsz / 128, MROWS / 128), 256, GI_SMEM>>>(b_ih);
    gru_persist_kernel<<<NCTA, 512, PS_SMEM>>>(b_hh, W_out, b_out, out);
    noop_kernel<<<1, 32>>>();
    noop_kernel<<<1, 32>>>();
}

// round 17
// speedup vs baseline: 1.0485x; 1.0485x over previous
#include <cuda_runtime.h>
#include <cuda_bf16.h>
#include <cstdint>
#include <math.h>

#define Bsz 512
#define Ssz 256
#define Esz 256
#define Hsz 512
#define Gsz 1536
#define Lsz 8
#define MROWS (Ssz * Bsz)
#define NCTA 128

// ---------------- device-global scratch (no runtime alloc) ------------------
__device__ __align__(16) float g_gi[(size_t)MROWS * Gsz];
__device__ __align__(16) float g_hf[Bsz * Hsz];          // final h only
__device__ __align__(16) __nv_bfloat16 g_hb_hi[2][Bsz * Hsz];
__device__ __align__(16) __nv_bfloat16 g_hb_lo[2][Bsz * Hsz];
__device__ __align__(16) __nv_bfloat16 g_x_hi[(size_t)MROWS * Esz];
__device__ __align__(16) __nv_bfloat16 g_x_lo[(size_t)MROWS * Esz];
__device__ __align__(16) __nv_bfloat16 g_whh_hi[Gsz * Hsz];
__device__ __align__(16) __nv_bfloat16 g_whh_lo[Gsz * Hsz];
__device__ __align__(16) __nv_bfloat16 g_wih_hi[Gsz * Esz];
__device__ __align__(16) __nv_bfloat16 g_wih_lo[Gsz * Esz];
__device__ unsigned int g_bars[8 * 32];   // per-b-group counters, 128B apart

// ---------------- PTX helpers (base-target only) -----------------------------
__device__ __forceinline__ uint32_t smem_u32(const void* p) {
    uint32_t a;
    asm("{ .reg .u64 t; cvta.to.shared.u64 t, %1; cvt.u32.u64 %0, t; }" : "=r"(a) : "l"(p));
    return a;
}
__device__ __forceinline__ void cp16(uint32_t dst, const void* src) {
    asm volatile("cp.async.cg.shared.global [%0], [%1], 16;" :: "r"(dst), "l"(src));
}
#define CP_COMMIT() asm volatile("cp.async.commit_group;" ::: "memory")
#define CP_WAIT(n)  asm volatile("cp.async.wait_group %0;" :: "n"(n) : "memory")

#define LDMX4(r, addr) \
    asm volatile("ldmatrix.sync.aligned.m8n8.x4.shared.b16 {%0,%1,%2,%3}, [%4];" \
        : "=r"((r)[0]), "=r"((r)[1]), "=r"((r)[2]), "=r"((r)[3]) : "r"(addr))

#define LDMX2(r, addr) \
    asm volatile("ldmatrix.sync.aligned.m8n8.x2.shared.b16 {%0,%1}, [%2];" \
        : "=r"((r)[0]), "=r"((r)[1]) : "r"(addr))

#define MMA_BF16(c, a, b0, b1) \
    asm volatile("mma.sync.aligned.m16n8k16.row.col.f32.bf16.bf16.f32 " \
        "{%0,%1,%2,%3}, {%4,%5,%6,%7}, {%8,%9}, {%0,%1,%2,%3};" \
        : "+f"((c)[0]), "+f"((c)[1]), "+f"((c)[2]), "+f"((c)[3]) \
        : "r"((a)[0]), "r"((a)[1]), "r"((a)[2]), "r"((a)[3]), "r"(b0), "r"(b1))

// ---------------- split helpers ----------------------------------------------
__device__ __forceinline__ void split2(float v, __nv_bfloat16& h, __nv_bfloat16& l) {
    h = __float2bfloat16_rn(v);
    l = __float2bfloat16_rn(v - __bfloat162float(h));
}
__device__ __forceinline__ void split_store4(float4 v, __nv_bfloat16* dh, __nv_bfloat16* dl) {
    __nv_bfloat16 h0,l0,h1,l1,h2,l2,h3,l3;
    split2(v.x,h0,l0); split2(v.y,h1,l1); split2(v.z,h2,l2); split2(v.w,h3,l3);
    __nv_bfloat162 p;
    p.x=h0; p.y=h1; ((__nv_bfloat162*)dh)[0]=p;
    p.x=h2; p.y=h3; ((__nv_bfloat162*)dh)[1]=p;
    p.x=l0; p.y=l1; ((__nv_bfloat162*)dl)[0]=p;
    p.x=l2; p.y=l3; ((__nv_bfloat162*)dl)[1]=p;
}

// tiny no-op kernels: keep the ncu capture window on gru_persist_kernel
__global__ void noop_kernel() {}

// ---------------------------------------------------------------------------
// prep: x split, W_hh split, W_ih split, h0/bars init, one launch
// ---------------------------------------------------------------------------
__global__ void prep_kernel(const float* __restrict__ x,
                            const float* __restrict__ W_hh,
                            const float* __restrict__ W_ih) {
    int blk = blockIdx.x, tid = threadIdx.x;
    if (blk < 32768) {
        size_t t = (size_t)blk * 256 + tid;
        size_t m = t >> 6;
        int e4 = (int)(t & 63) << 2;
        int s = (int)(m >> 9), b = (int)(m & 511);
        float4 v = *(const float4*)(x + ((size_t)b * Ssz + s) * Esz + e4);
        split_store4(v, g_x_hi + m * Esz + e4, g_x_lo + m * Esz + e4);
    } else if (blk < 33536) {
        int t = (blk - 32768) * 256 + tid;
        float4 v = *(const float4*)(W_hh + (size_t)t * 4);
        split_store4(v, g_whh_hi + (size_t)t * 4, g_whh_lo + (size_t)t * 4);
    } else if (blk < 33920) {
        int t = (blk - 33536) * 256 + tid;
        float4 v = *(const float4*)(W_ih + (size_t)t * 4);
        split_store4(v, g_wih_hi + (size_t)t * 4, g_wih_lo + (size_t)t * 4);
    } else {
        int i = (blk - 33920) * 256 + tid;   // < Bsz*Hsz/2
        __nv_bfloat162 z;
        z.x = __float2bfloat16_rn(0.0f); z.y = z.x;
        ((__nv_bfloat162*)g_hb_hi[0])[i] = z;
        ((__nv_bfloat162*)g_hb_lo[0])[i] = z;
        if (blk == 33920 && tid < 256) g_bars[tid] = 0u;
    }
}

// ---------------------------------------------------------------------------
// gi GEMM (HMMA), R14 champion: 8 chunks of K=32, double-buffered, 2 CTAs/SM.
// ---------------------------------------------------------------------------
#define GI_CH   40960
#define GI_SMEM (2 * GI_CH)
#define GAH 0
#define GAL 10240
#define GBH 20480
#define GBL 30720

__global__ void __launch_bounds__(256) gi_mma_kernel(const float* __restrict__ b_ih) {
    extern __shared__ __align__(16) char dsm[];
    __shared__ float s_bias[128];
    uint32_t sbase = smem_u32(dsm);
    int tid = threadIdx.x, wid = tid >> 5, lane = tid & 31;
    int n0 = blockIdx.x * 128;
    int m0 = blockIdx.y * 128;
    if (tid < 128) s_bias[tid] = b_ih[n0 + tid];

    int m_warp = (wid & 1) * 64;
    int n_warp = (wid >> 1) * 32;

    float acc[4][4][4];
#pragma unroll
    for (int mi = 0; mi < 4; mi++)
#pragma unroll
        for (int ni = 0; ni < 4; ni++)
#pragma unroll
            for (int e = 0; e < 4; e++) acc[mi][ni][e] = 0.0f;

    auto issue = [&](int c, int q) {
        uint32_t base = sbase + (uint32_t)q * GI_CH;
        int k0 = c * 32;
        for (int i = tid; i < 2048; i += 256) {
            int arr = i >> 10;
            int half = (i >> 9) & 1;
            int idx = i & 511;
            int row = idx >> 2, seg = idx & 3;
            const __nv_bfloat16* sp;
            if (arr == 0)
                sp = (half ? g_x_lo : g_x_hi) + ((size_t)(m0 + row)) * Esz + k0 + seg * 8;
            else
                sp = (half ? g_wih_lo : g_wih_hi) + ((size_t)(n0 + row)) * Esz + k0 + seg * 8;
            uint32_t dst = base + (uint32_t)(arr * 20480 + half * 10240 + row * 80 + seg * 16);
            cp16(dst, sp);
        }
        CP_COMMIT();
    };

    issue(0, 0);
    for (int c = 0; c < 8; c++) {
        int q = c & 1;
        CP_WAIT(0);
        __syncthreads();
        if (c < 7) issue(c + 1, q ^ 1);
        uint32_t bb = sbase + (uint32_t)q * GI_CH;
#pragma unroll
        for (int kk = 0; kk < 2; kk++) {
            int kb = kk * 32;
            uint32_t fa[2][4][4];
#pragma unroll
            for (int mi = 0; mi < 4; mi++) {
                uint32_t arow = (uint32_t)(m_warp + mi * 16 + (lane & 15));
                uint32_t aoff = arow * 80 + kb + ((lane >> 4) << 4);
                LDMX4(fa[0][mi], bb + GAH + aoff);
                LDMX4(fa[1][mi], bb + GAL + aoff);
            }
            uint32_t fb[2][2][4];
#pragma unroll
            for (int p = 0; p < 2; p++) {
                uint32_t brow = (uint32_t)(n_warp + p * 16 + (lane & 7) + ((lane >> 4) << 3));
                uint32_t boff = brow * 80 + kb + (((lane >> 3) & 1) << 4);
                LDMX4(fb[0][p], bb + GBH + boff);
                LDMX4(fb[1][p], bb + GBL + boff);
            }
#pragma unroll
            for (int t = 0; t < 3; t++) {
                int sa = (t == 2) ? 1 : 0, sb = (t == 1) ? 1 : 0;
#pragma unroll
                for (int mi = 0; mi < 4; mi++)
#pragma unroll
                    for (int ni = 0; ni < 4; ni++)
                        MMA_BF16(acc[mi][ni], fa[sa][mi],
                                 fb[sb][ni >> 1][(ni & 1) * 2],
                                 fb[sb][ni >> 1][(ni & 1) * 2 + 1]);
            }
        }
    }

#pragma unroll
    for (int mi = 0; mi < 4; mi++) {
        int m = m0 + m_warp + mi * 16 + (lane >> 2);
#pragma unroll
        for (int ni = 0; ni < 4; ni++) {
            int nl = n_warp + ni * 8 + (lane & 3) * 2;
            float2 v0 = make_float2(acc[mi][ni][0] + s_bias[nl],
                                    acc[mi][ni][1] + s_bias[nl + 1]);
            float2 v1 = make_float2(acc[mi][ni][2] + s_bias[nl],
                                    acc[mi][ni][3] + s_bias[nl + 1]);
            *(float2*)(g_gi + (size_t)m * Gsz + n0 + nl) = v0;
            *(float2*)(g_gi + (size_t)(m + 8) * Gsz + n0 + nl) = v1;
        }
    }
}

// ---------------------------------------------------------------------------
// Persistent GRU recurrence — R15 champion + hoisted LDSM addresses:
// all kk-dependent XOR/shift offsets (offa[kk][mi], offb[kk][gate]) are
// precomputed once before the step loop (chunk/step-invariant; only the
// hb/wb bases vary), removing ~10 ALU ops per kk from the inner loop
// (profile showed alu=17% of issue competing with LDSM/MMA).
// Arithmetic unchanged -> output bit-identical to R15.
// ---------------------------------------------------------------------------
#define WSPLIT 98304
#define WCHUNK 12288
#define WTOT   196608
#define HBUF   16384
#define HSPLIT 8192
#define PS_SMEM (WTOT + 2 * HBUF)   // 229376

__global__ void __launch_bounds__(256) gru_persist_kernel(
    const float* __restrict__ b_hh, const float* __restrict__ W_out,
    const float* __restrict__ b_out, float* __restrict__ out) {
    extern __shared__ __align__(16) char dsm[];
    __shared__ float s_bhh[96];
    uint32_t sbase = smem_u32(dsm);
    int tid = threadIdx.x, wid = tid >> 5, lane = tid & 31;
    int bx = blockIdx.x >> 4, jy = blockIdx.x & 15;
    int b0 = bx * 64, j0 = jy * 32;
    if (tid < 96) s_bhh[tid] = b_hh[(tid >> 5) * Hsz + j0 + (tid & 31)];

    // ---- resident W_hh tile: 12288 x 16B, XOR swizzle ----
    for (int i = tid; i < 12288; i += 256) {
        int p = i / 6144;
        int ii = i - p * 6144;
        int c = ii / 768;
        int r2 = ii - c * 768;
        int r = r2 >> 3, u = r2 & 7;
        int g = r >> 5, jr = r & 31;
        const __nv_bfloat16* sp = (p ? g_whh_lo : g_whh_hi) +
            ((size_t)(g * Hsz + j0 + jr)) * Hsz + c * 64 + u * 8;
        uint32_t dst = sbase + (uint32_t)(p * WSPLIT + c * WCHUNK + r * 128 +
                                          ((u ^ (r & 7)) << 4));
        cp16(dst, sp);
    }
    CP_COMMIT();
    CP_WAIT(0);
    __syncthreads();

    // 2M x 4N warp tiling (R15)
    const int m_warp = (wid & 1) * 32;
    const int jq = wid >> 1;
    const int jb = jq * 8 + (lane & 3) * 2;
    const int jcol = j0 + jb;
    unsigned int* bar = &g_bars[bx * 32];

    // ---- hoisted LDSM offsets: offa[kk][mi], offb[kk][gate] ----
    uint32_t offa_p[4][2], offb_p[4][3];
    {
        const uint32_t a_ub = (uint32_t)(lane >> 4);
        const uint32_t b_ub = (uint32_t)((lane >> 3) & 1);
#pragma unroll
        for (int kk = 0; kk < 4; kk++) {
#pragma unroll
            for (int mi = 0; mi < 2; mi++) {
                uint32_t arow = (uint32_t)(m_warp + mi * 16 + (lane & 15));
                uint32_t ua = (uint32_t)(kk * 2) + a_ub;
                offa_p[kk][mi] = arow * 128 + ((ua ^ (arow & 7)) << 4);
            }
#pragma unroll
            for (int g = 0; g < 3; g++) {
                uint32_t brow = (uint32_t)(g * 32 + jq * 8 + (lane & 7));
                uint32_t ub = (uint32_t)(kk * 2) + b_ub;
                offb_p[kk][g] = brow * 128 + ((ub ^ (brow & 7)) << 4);
            }
        }
    }

    // per-thread output coords: 4 rows (mi, ri), 2 j's
    float2 hp[2][2];
#pragma unroll
    for (int mi = 0; mi < 2; mi++)
#pragma unroll
        for (int ri = 0; ri < 2; ri++) hp[mi][ri] = make_float2(0.0f, 0.0f);

    float2 pg[3][2][2];
    auto prefetch_gi = [&](int s) {
        const float* base = g_gi + (size_t)s * Bsz * Gsz;
#pragma unroll
        for (int g = 0; g < 3; g++)
#pragma unroll
            for (int mi = 0; mi < 2; mi++)
#pragma unroll
                for (int ri = 0; ri < 2; ri++) {
                    int b = b0 + m_warp + mi * 16 + ri * 8 + (lane >> 2);
                    pg[g][mi][ri] = *(const float2*)(base + (size_t)b * Gsz +
                                                     g * Hsz + jcol);
                }
    };
    prefetch_gi(0);

    for (int s = 0; s < Ssz; s++) {
        int pin = s & 1, pout = pin ^ 1;
        const __nv_bfloat16* ah = g_hb_hi[pin];
        const __nv_bfloat16* al = g_hb_lo[pin];

        auto issue_h = [&](int c, int q) {
            uint32_t base = sbase + WTOT + (uint32_t)q * HBUF;
            for (int i = tid; i < 1024; i += 256) {
                int p = i >> 9;
                int idx = i & 511;
                int row = idx >> 3, u = idx & 7;
                const __nv_bfloat16* sp = (p ? al : ah) +
                    ((size_t)(b0 + row)) * Hsz + c * 64 + u * 8;
                uint32_t dst = base + (uint32_t)(p * HSPLIT + row * 128 +
                                                 ((u ^ (row & 7)) << 4));
                cp16(dst, sp);
            }
            CP_COMMIT();
        };

        float acc[2][3][4];   // [mi][gate][4]
#pragma unroll
        for (int mi = 0; mi < 2; mi++)
#pragma unroll
            for (int g = 0; g < 3; g++)
#pragma unroll
                for (int e = 0; e < 4; e++) acc[mi][g][e] = 0.0f;

        issue_h(0, 0);
        for (int c = 0; c < 8; c++) {
            int q = c & 1;
            CP_WAIT(0);
            __syncthreads();
            if (c < 7) issue_h(c + 1, q ^ 1);   // race-free: after the sync
            uint32_t hb = sbase + WTOT + (uint32_t)q * HBUF;
            uint32_t wb = sbase + (uint32_t)c * WCHUNK;

            uint32_t fa[2][2][2][4];   // [fq][split][mi][4]
            uint32_t fb[2][2][3][2];   // [fq][split][gate][2]
            auto load_frags = [&](int kk, int fq) {
#pragma unroll
                for (int mi = 0; mi < 2; mi++) {
                    uint32_t offa = offa_p[kk][mi];
                    LDMX4(fa[fq][0][mi], hb + offa);
                    LDMX4(fa[fq][1][mi], hb + HSPLIT + offa);
                }
#pragma unroll
                for (int g = 0; g < 3; g++) {
                    uint32_t offb = offb_p[kk][g];
                    LDMX2(fb[fq][0][g], wb + offb);
                    LDMX2(fb[fq][1][g], wb + WSPLIT + offb);
                }
            };

            load_frags(0, 0);
#pragma unroll
            for (int kk = 0; kk < 4; kk++) {
                int fq = kk & 1;
                if (kk < 3) load_frags(kk + 1, fq ^ 1);
#pragma unroll
                for (int t = 0; t < 3; t++) {
                    int sa = (t == 2) ? 1 : 0, sb = (t == 1) ? 1 : 0;
#pragma unroll
                    for (int mi = 0; mi < 2; mi++)
#pragma unroll
                        for (int g = 0; g < 3; g++)
                            MMA_BF16(acc[mi][g], fa[fq][sa][mi],
                                     fb[fq][sb][g][0], fb[fq][sb][g][1]);
                }
            }
        }

        // ---- register-resident GRU epilogue (fast-math sigmoid) ----
        __nv_bfloat16* hho = g_hb_hi[pout];
        __nv_bfloat16* hlo = g_hb_lo[pout];
#pragma unroll
        for (int mi = 0; mi < 2; mi++) {
#pragma unroll
            for (int ri = 0; ri < 2; ri++) {
                int b = b0 + m_warp + mi * 16 + ri * 8 + (lane >> 2);
                float hv[2];
#pragma unroll
                for (int e = 0; e < 2; e++) {
                    float dr = acc[mi][0][ri * 2 + e] + s_bhh[jb + e];
                    float dz = acc[mi][1][ri * 2 + e] + s_bhh[32 + jb + e];
                    float dn = acc[mi][2][ri * 2 + e] + s_bhh[64 + jb + e];
                    float gi_r = e ? pg[0][mi][ri].y : pg[0][mi][ri].x;
                    float gi_z = e ? pg[1][mi][ri].y : pg[1][mi][ri].x;
                    float gi_n = e ? pg[2][mi][ri].y : pg[2][mi][ri].x;
                    float hprev = e ? hp[mi][ri].y : hp[mi][ri].x;
                    float r = __fdividef(1.0f, 1.0f + __expf(-(gi_r + dr)));
                    float z = __fdividef(1.0f, 1.0f + __expf(-(gi_z + dz)));
                    float n = tanhf(gi_n + r * dn);
                    hv[e] = (1.0f - z) * n + z * hprev;
                }
                hp[mi][ri] = make_float2(hv[0], hv[1]);
                __nv_bfloat16 h0, l0, h1, l1;
                split2(hv[0], h0, l0);
                split2(hv[1], h1, l1);
                __nv_bfloat162 ph, pl;
                ph.x = h0; ph.y = h1;
                pl.x = l0; pl.y = l1;
                *(__nv_bfloat162*)(hho + (size_t)b * Hsz + jcol) = ph;
                *(__nv_bfloat162*)(hlo + (size_t)b * Hsz + jcol) = pl;
                if (s == Ssz - 1)
                    *(float2*)(g_hf + (size_t)b * Hsz + jcol) = make_float2(hv[0], hv[1]);
            }
        }

        // ---- publish FIRST, then prefetch next gi, then barrier wait ----
        __syncthreads();
        if (tid == 0) {
            asm volatile("red.release.gpu.global.add.u32 [%0], %1;"
                         :: "l"(bar), "r"(1u) : "memory");
        }
        if (s + 1 < Ssz) prefetch_gi(s + 1);

        if (tid == 0) {
            unsigned int target = (unsigned int)(s + 1) * 16u;
            unsigned int v;
            do {
                asm volatile("ld.acquire.gpu.u32 %0, [%1];" : "=r"(v) : "l"(bar));
            } while (v < target);
        }
        __syncthreads();
    }

    // ---- fused head: jy==0 CTAs compute logits+softmax for rows b0..b0+63 ----
    if (jy == 0) {
#pragma unroll 1
        for (int rr = 0; rr < 8; rr++) {
            int b = b0 + (wid << 3) + rr;
            const float* h = g_hf + (size_t)b * Hsz;
            float a8[Lsz];
#pragma unroll
            for (int l = 0; l < Lsz; l++) a8[l] = 0.0f;
            for (int j = lane; j < Hsz; j += 32) {
                float hv = h[j];
#pragma unroll
                for (int l = 0; l < Lsz; l++) a8[l] += hv * W_out[l * Hsz + j];
            }
#pragma unroll
            for (int l = 0; l < Lsz; l++)
#pragma unroll
                for (int o = 16; o > 0; o >>= 1)
                    a8[l] += __shfl_xor_sync(0xffffffff, a8[l], o);
            if (lane == 0) {
                float logits[Lsz], mx = -1e30f, sum = 0.0f;
#pragma unroll
                for (int l = 0; l < Lsz; l++) {
                    logits[l] = a8[l] + b_out[l];
                    mx = fmaxf(mx, logits[l]);
                }
#pragma unroll
                for (int l = 0; l < Lsz; l++) {
                    logits[l] = expf(logits[l] - mx);
                    sum += logits[l];
                }
                float inv = 1.0f / sum;
#pragma unroll
                for (int l = 0; l < Lsz; l++)
                    out[(size_t)b * Lsz + l] = logits[l] * inv;
            }
        }
    }
}

// ---------------------------------------------------------------------------
extern "C" void kernel_launch(void* const* d_in, const int* in_sizes, int n_in,
                              void* d_out, int out_size) {
    const float* x     = (const float*)d_in[0];
    const float* W_ih  = (const float*)d_in[1];
    const float* W_hh  = (const float*)d_in[2];
    const float* b_ih  = (const float*)d_in[3];
    const float* b_hh  = (const float*)d_in[4];
    const float* W_out = (const float*)d_in[5];
    const float* b_out = (const float*)d_in[6];
    float* out = (float*)d_out;

    cudaFuncSetAttribute(gi_mma_kernel, cudaFuncAttributeMaxDynamicSharedMemorySize, GI_SMEM);
    cudaFuncSetAttribute(gru_persist_kernel, cudaFuncAttributeMaxDynamicSharedMemorySize, PS_SMEM);

    // identical launch sequence so the ncu window stays on gru
    noop_kernel<<<1, 32>>>();
    prep_kernel<<<34432, 256>>>(x, W_hh, W_ih);
    gi_mma_kernel<<<dim3(Gsz / 128, MROWS / 128), 256, GI_SMEM>>>(b_ih);
    gru_persist_kernel<<<NCTA, 256, PS_SMEM>>>(b_hh, W_out, b_out, out);
    noop_kernel<<<1, 32>>>();
    noop_kernel<<<1, 32>>>();
}